// round 5
// baseline (speedup 1.0000x reference)
#include <cuda_runtime.h>
#include <cstdint>

// ---------------- problem constants ----------------
#define NE   8
#define NT   16384
#define NIN  2048
#define NOUT 2048

// ---------------- GEMM tiling ----------------
#define BM 128
#define BN 256
#define BK 32
#define KITERS (NIN / BK)            // 64
#define STAGES 4
#define A_STAGE_BYTES (BM * BK * 4)  // 16384
#define B_STAGE_BYTES (BN * BK * 4)  // 32768
#define STAGE_BYTES (A_STAGE_BYTES + B_STAGE_BYTES)   // 49152
#define SMEM_CTRL 1024
#define SMEM_TOTAL (SMEM_CTRL + STAGES * STAGE_BYTES) // 197632
#define NTHREADS 320                 // 8 compute warps + 2 producer warps

// ---------------- scratch: tf32-rounded, fragment-native layouts ----------------
// g_A: [b(128)][kc(256)][mtile(8)][t(32)*4 + j]   (4 KB per (b,kc))
// g_W: [nb(64)][kc(256)][ntile(32)][t(32)*2 + j]  (8 KB per (nb,kc))
__device__ float g_A[(size_t)NT * NIN];
__device__ float g_W[(size_t)NE * NOUT * NIN];

// ---------------- helpers (all plain-sm_103-legal) ----------------
__device__ __forceinline__ uint32_t smem_u32(const void* p) {
    uint32_t a;
    asm("{ .reg .u64 t; cvta.to.shared.u64 t, %1; cvt.u32.u64 %0, t; }" : "=r"(a) : "l"(p));
    return a;
}

__device__ __forceinline__ float tf32r(float f) {   // round-to-nearest tf32 (unbiased)
    uint32_t r;
    asm("cvt.rna.tf32.f32 %0, %1;" : "=r"(r) : "f"(f));
    return __uint_as_float(r);
}

__device__ __forceinline__ void cp16(uint32_t smem_dst, const float* gsrc) {
    asm volatile("cp.async.cg.shared.global [%0], [%1], 16;" :: "r"(smem_dst), "l"(gsrc));
}

#define MBAR_INIT(a, c) \
    asm volatile("mbarrier.init.shared.b64 [%0], %1;" :: "r"(a), "r"(c) : "memory")
#define MBAR_ARRIVE(a) \
    asm volatile("mbarrier.arrive.shared.b64 _, [%0];" :: "r"(a) : "memory")
#define CP_MBAR_ARRIVE(a) \
    asm volatile("cp.async.mbarrier.arrive.noinc.shared.b64 [%0];" :: "r"(a) : "memory")

#define MBAR_WAIT(addr, ph) do {                                                   \
    asm volatile("{\n\t.reg .pred P1;\n\t"                                         \
        "WL%=:\n\t"                                                                \
        "mbarrier.try_wait.parity.acquire.cta.shared::cta.b64 P1, [%0], %1, 0x989680;\n\t" \
        "@P1 bra.uni WD%=;\n\t"                                                    \
        "bra.uni WL%=;\n\t"                                                        \
        "WD%=:\n\t}"                                                               \
        :: "r"(addr), "r"(ph) : "memory");                                         \
} while (0)

__device__ __forceinline__ void lds128(uint32_t* r, uint32_t addr) {
    asm volatile("ld.shared.v4.b32 {%0,%1,%2,%3}, [%4];"
                 : "=r"(r[0]), "=r"(r[1]), "=r"(r[2]), "=r"(r[3]) : "r"(addr));
}
__device__ __forceinline__ void lds64(uint32_t* r, uint32_t addr) {
    asm volatile("ld.shared.v2.b32 {%0,%1}, [%2];"
                 : "=r"(r[0]), "=r"(r[1]) : "r"(addr));
}

__device__ __forceinline__ void mma_tf32(float* d, const uint32_t* a, const uint32_t* b) {
    asm volatile(
        "mma.sync.aligned.m16n8k8.row.col.f32.tf32.tf32.f32 "
        "{%0,%1,%2,%3}, {%4,%5,%6,%7}, {%8,%9}, {%0,%1,%2,%3};"
        : "+f"(d[0]), "+f"(d[1]), "+f"(d[2]), "+f"(d[3])
        : "r"(a[0]), "r"(a[1]), "r"(a[2]), "r"(a[3]), "r"(b[0]), "r"(b[1]));
}

// ---------------- merged pre-pass: MLP-8 per thread, A-half + W-half ------------
// A half (blocks [0,4096)): thread handles 2 rows x 16 cols (two kc units).
// W half (blocks [4096,8192)): thread handles 1 row x 32 cols (four kc units),
//   fully contiguous 128B global read.
__global__ void __launch_bounds__(256) prep_kernel(const float* __restrict__ x,
                                                   const float* __restrict__ w) {
    if (blockIdx.x < 4096) {
        // ---------------- A: x -> g_A fragment-native ----------------
        uint32_t gid = blockIdx.x * 256 + threadIdx.x;   // [0, 2^20)
        int lrg   = gid & 7;
        int mtile = (gid >> 3) & 7;
        int kcq   = (gid >> 6) & 127;                    // kc pair index
        int b     = gid >> 13;                           // [0,128)
        int row0  = b * 128 + mtile * 16 + lrg;
        int c     = kcq * 16;

        const float* r0 = x + (size_t)row0 * NIN + c;
        const float* r1 = r0 + (size_t)8 * NIN;
        float4 a0 = *(const float4*)(r0);                // 8 independent 16B loads
        float4 a1 = *(const float4*)(r0 + 4);
        float4 a2 = *(const float4*)(r0 + 8);
        float4 a3 = *(const float4*)(r0 + 12);
        float4 b0 = *(const float4*)(r1);
        float4 b1 = *(const float4*)(r1 + 4);
        float4 b2 = *(const float4*)(r1 + 8);
        float4 b3 = *(const float4*)(r1 + 12);

        float* dst0 = g_A + ((((size_t)b * 256 + 2 * kcq) * 8 + mtile) * 128) + lrg * 16;
        float* dst1 = dst0 + 1024;                       // next kc unit (+8*128 floats)
        float4 o;
        // kc unit 0: cols c..c+7  (u0=a0,u1=a1,v0=b0,v1=b1)
        o.x = tf32r(a0.x); o.y = tf32r(b0.x); o.z = tf32r(a1.x); o.w = tf32r(b1.x);
        *(float4*)(dst0 + 0)  = o;
        o.x = tf32r(a0.y); o.y = tf32r(b0.y); o.z = tf32r(a1.y); o.w = tf32r(b1.y);
        *(float4*)(dst0 + 4)  = o;
        o.x = tf32r(a0.z); o.y = tf32r(b0.z); o.z = tf32r(a1.z); o.w = tf32r(b1.z);
        *(float4*)(dst0 + 8)  = o;
        o.x = tf32r(a0.w); o.y = tf32r(b0.w); o.z = tf32r(a1.w); o.w = tf32r(b1.w);
        *(float4*)(dst0 + 12) = o;
        // kc unit 1: cols c+8..c+15 (u0=a2,u1=a3,v0=b2,v1=b3)
        o.x = tf32r(a2.x); o.y = tf32r(b2.x); o.z = tf32r(a3.x); o.w = tf32r(b3.x);
        *(float4*)(dst1 + 0)  = o;
        o.x = tf32r(a2.y); o.y = tf32r(b2.y); o.z = tf32r(a3.y); o.w = tf32r(b3.y);
        *(float4*)(dst1 + 4)  = o;
        o.x = tf32r(a2.z); o.y = tf32r(b2.z); o.z = tf32r(a3.z); o.w = tf32r(b3.z);
        *(float4*)(dst1 + 8)  = o;
        o.x = tf32r(a2.w); o.y = tf32r(b2.w); o.z = tf32r(a3.w); o.w = tf32r(b3.w);
        *(float4*)(dst1 + 12) = o;
    } else {
        // ---------------- W: w -> g_W fragment-native ----------------
        uint32_t gid = (blockIdx.x - 4096) * 256 + threadIdx.x;   // [0, 2^20)
        int ln    = gid & 7;
        int ntile = (gid >> 3) & 31;
        int kcg   = (gid >> 8) & 63;                     // kc quad index
        int nb    = gid >> 14;                           // [0,64)
        int grow  = nb * 256 + ntile * 8 + ln;
        int c     = kcg * 32;

        const float* r = w + (size_t)grow * NIN + c;
        float4 v[8];                                     // 128B contiguous read
        #pragma unroll
        for (int i = 0; i < 8; i++) v[i] = *(const float4*)(r + i * 4);

        #pragma unroll
        for (int q = 0; q < 4; q++) {                    // kc = 4*kcg + q
            float4 v0 = v[2 * q];                        // cols 8q..8q+3
            float4 v1 = v[2 * q + 1];                    // cols 8q+4..8q+7
            float* dst = g_W + ((((size_t)nb * 256 + 4 * kcg + q) * 32 + ntile) * 64)
                         + ln * 8;
            float4 o;
            o.x = tf32r(v0.x); o.y = tf32r(v1.x); o.z = tf32r(v0.y); o.w = tf32r(v1.y);
            *(float4*)(dst + 0) = o;
            o.x = tf32r(v0.z); o.y = tf32r(v1.z); o.z = tf32r(v0.w); o.w = tf32r(v1.w);
            *(float4*)(dst + 4) = o;
        }
    }
}

// ---------------- main grouped GEMM: warp-specialized mbarrier pipeline ---------
__global__ void __launch_bounds__(NTHREADS, 1) gemm_kernel(
        const float* __restrict__ bias,
        const int*   __restrict__ tpe,
        float*       __restrict__ out) {
    extern __shared__ __align__(16) char smem[];

    const int e  = blockIdx.z;
    const int mt = blockIdx.y;
    const int nt = blockIdx.x;

    int start = 0, mycnt = 0;
    #pragma unroll
    for (int i = 0; i < NE; i++) {
        int cc = __ldg(tpe + i);
        if (i < e) start += cc;
        if (i == e) mycnt = cc;
    }
    if (mt * BM >= mycnt) return;

    const int tid  = threadIdx.x;
    const int b    = (start >> 7) + mt;
    const int nb   = e * 8 + nt;
    const int m0   = start + mt * BM;

    const uint32_t sb     = smem_u32(smem);
    const uint32_t fullb  = sb;              // STAGES x 8B
    const uint32_t emptyb = sb + 64;         // STAGES x 8B
    const uint32_t dbase  = sb + SMEM_CTRL;

    const float* Ab = g_A + (size_t)b  * 256 * 1024;
    const float* Bb = g_W + (size_t)nb * 256 * 2048;

    if (tid == 0) {
        #pragma unroll
        for (int s = 0; s < STAGES; s++) {
            MBAR_INIT(fullb + s * 8, 64);
            MBAR_INIT(emptyb + s * 8, 256);
        }
    }
    __syncthreads();

    if (tid >= 256) {
        // ================= producer warps (2 warps, 64 threads) =================
        const int ptid = tid - 256;
        #pragma unroll 1
        for (int k = 0; k < KITERS; k++) {
            const int s = k & (STAGES - 1);
            if (k >= STAGES) MBAR_WAIT(emptyb + s * 8, ((k >> 2) - 1) & 1);
            const float* As = Ab + (size_t)k * 4096;
            const float* Bs = Bb + (size_t)k * 8192;
            const uint32_t dA = dbase + s * STAGE_BYTES;
            const uint32_t dB = dA + A_STAGE_BYTES;
            #pragma unroll
            for (int i = 0; i < 16; i++)
                cp16(dA + (ptid + i * 64) * 16, As + (ptid + i * 64) * 4);
            #pragma unroll
            for (int i = 0; i < 32; i++)
                cp16(dB + (ptid + i * 64) * 16, Bs + (ptid + i * 64) * 4);
            CP_MBAR_ARRIVE(fullb + s * 8);
        }
    } else {
        // ================= compute warps (8 warps, 256 threads) =================
        const int lane = tid & 31;
        const int wid  = tid >> 5;
        const int wm   = wid & 1;
        const int wn   = wid >> 1;

        float acc[4][8][4];
        #pragma unroll
        for (int i = 0; i < 4; i++)
            #pragma unroll
            for (int j = 0; j < 8; j++)
                #pragma unroll
                for (int k = 0; k < 4; k++) acc[i][j][k] = 0.0f;

        #pragma unroll 1
        for (int k = 0; k < KITERS; k++) {
            const int s = k & (STAGES - 1);
            MBAR_WAIT(fullb + s * 8, (k >> 2) & 1);
            const uint32_t aBase = dbase + s * STAGE_BYTES;
            const uint32_t bBase = aBase + A_STAGE_BYTES;
            #pragma unroll
            for (int kcl = 0; kcl < 4; kcl++) {
                uint32_t af[4][4], bf[8][2];
                #pragma unroll
                for (int i = 0; i < 4; i++)
                    lds128(af[i], aBase + ((kcl * 8 + wm * 4 + i) * 128 + lane * 4) * 4);
                #pragma unroll
                for (int j = 0; j < 8; j++)
                    lds64(bf[j], bBase + ((kcl * 32 + wn * 8 + j) * 64 + lane * 2) * 4);
                #pragma unroll
                for (int i = 0; i < 4; i++)
                    #pragma unroll
                    for (int j = 0; j < 8; j++)
                        mma_tf32(acc[i][j], af[i], bf[j]);
            }
            MBAR_ARRIVE(emptyb + s * 8);
        }

        // ---- epilogue: bias add + fp32 store ----
        const int ncol0 = nt * BN + wn * 64;
        const float* bptr = bias + (size_t)e * NOUT + ncol0;
        #pragma unroll
        for (int j = 0; j < 8; j++) {
            const int cb = j * 8 + (lane & 3) * 2;
            const float bx = __ldg(bptr + cb);
            const float by = __ldg(bptr + cb + 1);
            #pragma unroll
            for (int i = 0; i < 4; i++) {
                const int r0 = wm * 64 + i * 16 + (lane >> 2);
                if (mt * BM + r0 < mycnt) {
                    float2 v = make_float2(acc[i][j][0] + bx, acc[i][j][1] + by);
                    *(float2*)(out + (size_t)(m0 + r0) * NOUT + ncol0 + cb) = v;
                }
                if (mt * BM + r0 + 8 < mycnt) {
                    float2 v = make_float2(acc[i][j][2] + bx, acc[i][j][3] + by);
                    *(float2*)(out + (size_t)(m0 + r0 + 8) * NOUT + ncol0 + cb) = v;
                }
            }
        }
    }
}

// ---------------- host launch ----------------
extern "C" void kernel_launch(void* const* d_in, const int* in_sizes, int n_in,
                              void* d_out, int out_size) {
    const float* x    = (const float*)d_in[0];
    const float* w    = (const float*)d_in[1];
    const float* bias = (const float*)d_in[2];
    const int*   tpe  = (const int*)d_in[3];
    float*       out  = (float*)d_out;

    prep_kernel<<<8192, 256>>>(x, w);                      // merged A+W pre-pass

    cudaFuncSetAttribute(gemm_kernel,
                         cudaFuncAttributeMaxDynamicSharedMemorySize, SMEM_TOTAL);
    dim3 grid(NOUT / BN, NT / BM, NE);                     // (8, 128, 8), ragged exit
    gemm_kernel<<<grid, NTHREADS, SMEM_TOTAL>>>(bias, tpe, out);
}